// round 16
// baseline (speedup 1.0000x reference)
#include <cuda_runtime.h>
#include <cuda_bf16.h>
#include <cstdint>

typedef unsigned long long u64;

// Cross-block scratch (no allocations allowed -> __device__ globals)
__device__ float2 g_v[4][4096];       // 4 columns of the circuit unitary
__device__ u64 g_sX[2][4][2048];      // double-buffered per-column staging, X
__device__ u64 g_sY[2][4][2048];      // double-buffered per-column staging, Y
__device__ unsigned g_flag = 0;       // sim-done counter (target 8)
__device__ int g_done2 = 0;           // output-blocks-passed-spin counter

// ---------------- f32x2 packed helpers ----------------
__device__ __forceinline__ u64 pack2(float x, float y) {
    u64 u; asm("mov.b64 %0, {%1,%2};" : "=l"(u) : "f"(x), "f"(y)); return u;
}
__device__ __forceinline__ float2 unpack2(u64 u) {
    float2 v; asm("mov.b64 {%0,%1}, %2;" : "=f"(v.x), "=f"(v.y) : "l"(u)); return v;
}
__device__ __forceinline__ u64 swap2(u64 u) {
    float2 v = unpack2(u); return pack2(v.y, v.x);
}
__device__ __forceinline__ u64 fma2(u64 a, u64 b, u64 c) {
    u64 d; asm("fma.rn.f32x2 %0, %1, %2, %3;" : "=l"(d) : "l"(a), "l"(b), "l"(c)); return d;
}
__device__ __forceinline__ u64 mul2(u64 a, u64 b) {
    u64 d; asm("mul.rn.f32x2 %0, %1, %2;" : "=l"(d) : "l"(a), "l"(b)); return d;
}
__device__ __forceinline__ float ldcg(const float* p) {
    float v; asm volatile("ld.global.cg.f32 %0, [%1];" : "=f"(v) : "l"(p)); return v;
}
__device__ __forceinline__ void stcg64(u64* p, u64 v) {
    asm volatile("st.global.cg.b64 [%0], %1;" :: "l"(p), "l"(v));
}
__device__ __forceinline__ void red_release_add(unsigned* p, unsigned v) {
    asm volatile("red.release.gpu.global.add.u32 [%0], %1;" :: "l"(p), "r"(v) : "memory");
}
__device__ __forceinline__ unsigned ld_acquire(const unsigned* p) {
    unsigned v;
    asm volatile("ld.acquire.gpu.global.u32 %0, [%1];" : "=r"(v) : "l"(p) : "memory");
    return v;
}
__device__ __forceinline__ float2 cmulf(float2 a, float2 b) {
    return make_float2(a.x * b.x - a.y * b.y, a.x * b.y + a.y * b.x);
}

// ---------------- cluster / mbarrier helpers ----------------
__device__ __forceinline__ uint32_t smem32(const void* p) {
    uint32_t a;
    asm("{ .reg .u64 t; cvta.to.shared.u64 t, %1; cvt.u32.u64 %0, t; }"
        : "=r"(a) : "l"(p));
    return a;
}
__device__ __forceinline__ void mbar_init(uint32_t a, unsigned cnt) {
    asm volatile("mbarrier.init.shared.b64 [%0], %1;" :: "r"(a), "r"(cnt) : "memory");
}
__device__ __forceinline__ void mbar_arrive_peer(uint32_t a, unsigned peer) {
    asm volatile(
        "{\n\t.reg .b32 ra;\n\t"
        "mapa.shared::cluster.u32 ra, %0, %1;\n\t"
        "mbarrier.arrive.release.cluster.shared::cluster.b64 _, [ra];\n\t}"
        :: "r"(a), "r"(peer) : "memory");
}
__device__ __forceinline__ void mbar_wait(uint32_t a, unsigned parity) {
    asm volatile(
        "{\n\t.reg .pred P;\n\t"
        "W%=:\n\t"
        "mbarrier.try_wait.parity.acquire.cluster.shared::cta.b64 P, [%0], %1;\n\t"
        "@P bra.uni D%=;\n\t"
        "bra.uni W%=;\n\t"
        "D%=:\n\t}"
        :: "r"(a), "r"(parity) : "memory");
}
#define CLUSTER_ARRIVE() asm volatile("barrier.cluster.arrive.aligned;" ::: "memory")
#define CLUSTER_WAIT()   asm volatile("barrier.cluster.wait.aligned;" ::: "memory")

// ---------------- shared memory (dynamic, ~66KB) ----------------
// Real-RY coef block per gate (4 u64, 32B): [0]=cs=(c,c), [1]=coA=(-s,-s),
// [2]=coB=(s,s), [3]=coP=(-s,s).
struct SimSmem {
    u64 coef[96 * 4];               // real RY coefficients
    float2 rawu[48];                // raw complex 2x2 of layer-0 gates
    float2 ry0[8];                  // (cos th/2, sin th/2) of wire-0 gates
    float2 eph[96];                 // e^{+i phi/2} per gate
    float2 eom[96];                 // e^{+i omega/2} per gate
    float2 tabA[8][128];            // diag factor tables, y bits 0..6
    float2 tabB[8][64];             // diag factor tables, y bits 6..11
    u64 aX[1024]; u64 aY[1024];     // local transpose A staging
    u64 bX[1024]; u64 bY[1024];     // local transpose B staging
    u64 cX[1024]; u64 cY[1024];     // own-half mirror for self-term gather
    u64 mbar[2];                    // double-buffered cross-CTA mbarriers
};

// ---------------------------------------------------------------------------
// Layout identical to R12/R14 (passing): amp n: lam=n0, p=n1, t0..t4=n2..n6,
// t5..t8=n7..n10, r=n11. Wire w acts on bit 11-w.
// Rot = RZ(omega) RY(theta) RZ(phi): per layer L = Omega * (RY tensor) * Phi
// with Omega/Phi diagonal. Diagonals are folded into per-exchange tables:
// F_l(y) = Omegafac_l(sigma(y)) * Phifac_{l+1}(y),  sigma(y)=y^(y>>1),
// factorized as tabA_l[y&127] * tabB_l[y>>6]. Phase gates are pure real RY.
// Layer 0 is fully analytic (incl. wire 0 + CNOT perm + Phi_1); exchanges run
// for l=1..7 with parity ((l-1)>>1)&1.
// ---------------------------------------------------------------------------

__device__ __forceinline__ void gate_pair(u64 AX[2], u64 AY[2], const u64* cc) {
    u64 cs = cc[0], coA = cc[1], coB = cc[2];
    u64 x0 = AX[0], y0 = AY[0], x1 = AX[1], y1 = AY[1];
    AX[0] = fma2(coA, x1, mul2(cs, x0));
    AY[0] = fma2(coA, y1, mul2(cs, y0));
    AX[1] = fma2(coB, x0, mul2(cs, x1));
    AY[1] = fma2(coB, y0, mul2(cs, y1));
}

__device__ __forceinline__ void gate_pck(u64 AX[2], u64 AY[2], const u64* cc) {
    u64 cs = cc[0], coP = cc[3];
    #pragma unroll
    for (int p = 0; p < 2; p++) {
        u64 px = swap2(AX[p]), py = swap2(AY[p]);
        AX[p] = fma2(coP, px, mul2(cs, AX[p]));
        AY[p] = fma2(coP, py, mul2(cs, AY[p]));
    }
}

template<int LM, int K>
__device__ __forceinline__ void gate_lane(u64 AX[2], u64 AY[2], const u64* cc, int t) {
    u64 cs = cc[0];
    u64 co = ((t >> K) & 1) ? cc[2] : cc[1];
    #pragma unroll
    for (int p = 0; p < 2; p++) {
        u64 px = __shfl_xor_sync(0xffffffffu, AX[p], LM);
        u64 py = __shfl_xor_sync(0xffffffffu, AY[p], LM);
        AX[p] = fma2(co, px, mul2(cs, AX[p]));
        AY[p] = fma2(co, py, mul2(cs, AY[p]));
    }
}

// Global/smem staging float address of natural amp m (per column) — R12 map:
__device__ __forceinline__ int Gaddr(int m) {
    return ((m >> 7) & 1) | (((m >> 2) & 0x1F) << 1) | (((m >> 9) & 1) << 6)
         | (((m >> 10) & 1) << 7) | ((m & 1) << 8) | (((m >> 1) & 1) << 9)
         | (((m >> 8) & 1) << 10) | (((m >> 11) & 1) << 11);
}

__device__ __forceinline__ float2 facsel(float2 e, int bit) {
    return bit ? e : make_float2(e.x, -e.y);
}

__global__ __launch_bounds__(512, 1) __cluster_dims__(2, 1, 1)
void fused_kernel(
    const float* __restrict__ weights, const float* __restrict__ head_w,
    const float* __restrict__ head_b, const float* __restrict__ sb,
    float* __restrict__ out, int B, int nOut)
{
    extern __shared__ char smem_raw[];
    const int t = threadIdx.x;
    const int bid = blockIdx.x;

    if (bid < 8) {
        // ================= SIM BLOCK (col = bid>>1, half r = bid&1) ========
        SimSmem* sm = (SimSmem*)smem_raw;
        const int col = bid >> 1;
        const int r = bid & 1;
        const int b0 = (col >> 1) & 1;
        const int b1 = col & 1;
        const unsigned peer = 1u - (unsigned)r;
        const uint32_t mb0 = smem32(&sm->mbar[0]);
        const uint32_t mb1 = smem32(&sm->mbar[1]);

        if (t < 96) {
            int l = t / 12, w = t % 12;
            float phi = weights[t * 3 + 0];
            float th  = weights[t * 3 + 1];
            float om  = weights[t * 3 + 2];
            float st, ct; sincosf(th * 0.5f, &st, &ct);
            float sphi, cphi; sincosf(phi * 0.5f, &sphi, &cphi);
            float som, com; sincosf(om * 0.5f, &som, &com);
            u64* c = sm->coef + t * 4;
            c[0] = pack2(ct, ct);
            c[1] = pack2(-st, -st);
            c[2] = pack2(st, st);
            c[3] = pack2(-st, st);
            sm->eph[t] = make_float2(cphi, sphi);
            sm->eom[t] = make_float2(com, som);
            if (w == 0) sm->ry0[l] = make_float2(ct, st);
            if (l == 0) {
                float cp = cphi * com - sphi * som, sp = sphi * com + cphi * som;
                float cd = cphi * com + sphi * som, sd = sphi * com - cphi * som;
                sm->rawu[w * 4 + 0] = make_float2( cp * ct, -sp * ct);
                sm->rawu[w * 4 + 1] = make_float2(-cd * st, -sd * st);
                sm->rawu[w * 4 + 2] = make_float2( cd * st, -sd * st);
                sm->rawu[w * 4 + 3] = make_float2( cp * ct,  sp * ct);
            }
        }
        if (t == 0) { mbar_init(mb0, 1); mbar_init(mb1, 1); }
        __syncthreads();

        // ---- build diag tables: F_l = Omega_l(sigma(y)) * Phi_{l+1}(y) ----
        for (int e = t; e < 1536; e += 512) {
            int l = e / 192;
            int i = e - l * 192;
            float2 v = make_float2(1.f, 0.f);
            if (i < 128) {                       // A_l: y bits 0..6, wires 6..11
                #pragma unroll
                for (int j = 0; j < 6; j++) {
                    int w = 11 - j;
                    if (l > 0) {
                        int mb = ((i >> j) ^ (i >> (j + 1))) & 1;
                        v = cmulf(v, facsel(sm->eom[l * 12 + w], mb));
                    }
                    if (l < 7) {
                        int yb = (i >> j) & 1;
                        v = cmulf(v, facsel(sm->eph[(l + 1) * 12 + w], yb));
                    }
                }
                sm->tabA[l][i] = v;
            } else {                              // B_l: y bits 6..11, wires 0..5
                int b = i - 128;
                if (l > 0) {
                    #pragma unroll
                    for (int j = 6; j < 11; j++) {
                        int w = 11 - j;
                        int mb = ((b >> (j - 6)) ^ (b >> (j - 5))) & 1;
                        v = cmulf(v, facsel(sm->eom[l * 12 + w], mb));
                    }
                    v = cmulf(v, facsel(sm->eom[l * 12 + 0], (b >> 5) & 1)); // m11
                }
                if (l < 7) {
                    #pragma unroll
                    for (int j = 6; j < 12; j++) {
                        int w = 11 - j;
                        int yb = (b >> (j - 6)) & 1;
                        v = cmulf(v, facsel(sm->eph[(l + 1) * 12 + w], yb));
                    }
                }
                sm->tabB[l][b] = v;
            }
        }
        __syncthreads();
        CLUSTER_ARRIVE();
        CLUSTER_WAIT();

        // layer-invariant addresses (verbatim R12)
        const int baseA = ((t & 0x7F) << 1) | ((t >> 7) & 1) | (((t >> 8) & 1) << 10);
        const int baseB = ((t >> 5) & 1) | ((t & 0x1F) << 1)
                        | (((t >> 7) & 1) << 8) | (((t >> 8) & 1) << 9)
                        | (((t >> 6) & 1) << 10);
        const int nb = ((t & 0x1F) << 2) | (((t >> 5) & 0xF) << 7) | (r << 11);
        const int gb = Gaddr((nb ^ (nb >> 1)) & 0xFFF);
        const int abase = (t & 31) << 2;                 // tabA index base
        const int bidx = ((t >> 4) & 31) | (r << 5);     // tabB index (fixed)

        float* fAX = (float*)sm->aX; float* fAY = (float*)sm->aY;
        float* fBX = (float*)sm->bX; float* fBY = (float*)sm->bY;
        float* csX = (float*)sm->cX; float* csY = (float*)sm->cY;

        // ---- analytic layer 0 (full layer incl wire 0 + perm + Phi_1) ----
        u64 AX[2], AY[2];
        {
            const float2* RU = sm->rawu;
            int x0 = t & 1, x1 = (t >> 1) & 1, x2 = (t >> 2) & 1, x3 = (t >> 3) & 1;
            int x4 = (t >> 4) & 1, x5 = (t >> 5) & 1, x6 = (t >> 6) & 1;
            int x7 = (t >> 7) & 1, x8 = (t >> 8) & 1;
            float2 P = RU[0 * 4 + r * 2 + b0];
            P = cmulf(P, RU[1 * 4 + (x8 ^ r) * 2 + b1]);
            P = cmulf(P, RU[2 * 4 + (x7 ^ x8) * 2]);
            P = cmulf(P, RU[3 * 4 + (x6 ^ x7) * 2]);
            P = cmulf(P, RU[4 * 4 + (x5 ^ x6) * 2]);
            P = cmulf(P, RU[5 * 4 + (x4 ^ x5) * 2]);
            P = cmulf(P, RU[6 * 4 + (x3 ^ x4) * 2]);
            P = cmulf(P, RU[7 * 4 + (x2 ^ x3) * 2]);
            P = cmulf(P, RU[8 * 4 + (x1 ^ x2) * 2]);
            P = cmulf(P, RU[9 * 4 + (x0 ^ x1) * 2]);
            P = cmulf(P, sm->tabB[0][bidx]);
            #pragma unroll
            for (int p = 0; p < 2; p++) {
                float2 Q  = cmulf(P, RU[10 * 4 + (p ^ x0) * 2]);   // m1 = p^t0
                float2 a0 = cmulf(Q, RU[11 * 4 + p * 2]);          // m0 = 0^p
                float2 a1 = cmulf(Q, RU[11 * 4 + (1 ^ p) * 2]);    // m0 = 1^p
                a0 = cmulf(a0, sm->tabA[0][abase | (p << 1)]);
                a1 = cmulf(a1, sm->tabA[0][abase | (p << 1) | 1]);
                AX[p] = pack2(a0.x, a1.x);
                AY[p] = pack2(a0.y, a1.y);
            }
        }

        #pragma unroll 1
        for (int l = 1; l < 8; l++) {
            const u64* CG = sm->coef + l * 12 * 4;
            // ---- real-RY gates on bits 0..6 (wires 11..5) ----
            gate_pck (AX, AY, CG + 11 * 4);
            gate_pair(AX, AY, CG + 10 * 4);
            gate_lane<1, 0>(AX, AY, CG + 9 * 4, t);
            gate_lane<2, 1>(AX, AY, CG + 8 * 4, t);
            gate_lane<4, 2>(AX, AY, CG + 7 * 4, t);
            gate_lane<8, 3>(AX, AY, CG + 6 * 4, t);
            gate_lane<16, 4>(AX, AY, CG + 5 * 4, t);
            // ---- transpose A: (lam,p) <-> (n9,n10) ----
            sm->aX[t] = AX[0]; sm->aX[512 + t] = AX[1];
            sm->aY[t] = AY[0]; sm->aY[512 + t] = AY[1];
            __syncthreads();
            #pragma unroll
            for (int p = 0; p < 2; p++) {
                int a = baseA ^ (p << 9);
                AX[p] = pack2(fAX[a], fAX[a ^ 256]);
                AY[p] = pack2(fAY[a], fAY[a ^ 256]);
            }
            gate_pck (AX, AY, CG + 2 * 4);
            gate_pair(AX, AY, CG + 1 * 4);
            // ---- transpose B: (lam,p) <-> (n7,n8) ----
            sm->bX[t] = AX[0]; sm->bX[512 + t] = AX[1];
            sm->bY[t] = AY[0]; sm->bY[512 + t] = AY[1];
            __syncthreads();
            #pragma unroll
            for (int p = 0; p < 2; p++) {
                int a = baseB ^ (p << 7);
                AX[p] = pack2(fBX[a], fBX[a ^ 64]);
                AY[p] = pack2(fBY[a], fBY[a ^ 64]);
            }
            gate_pck (AX, AY, CG + 4 * 4);
            gate_pair(AX, AY, CG + 3 * 4);
            // ---- exchange: wire-0 RY (branch r) x diag F_l, + CNOT perm ----
            u64* guX = g_sX[l & 1][col];
            u64* guY = g_sY[l & 1][col];
            const float* gfX = (const float*)guX;
            const float* gfY = (const float*)guY;
            stcg64(&guX[(r << 10) | t], AX[0]);
            stcg64(&guX[(r << 10) | 512 | t], AX[1]);
            stcg64(&guY[(r << 10) | t], AY[0]);
            stcg64(&guY[(r << 10) | 512 | t], AY[1]);
            sm->cX[t] = AX[0]; sm->cX[512 + t] = AX[1];
            sm->cY[t] = AY[0]; sm->cY[512 + t] = AY[1];
            __syncthreads();
            const uint32_t mb = (l & 1) ? mb1 : mb0;
            const unsigned par = (unsigned)(((l - 1) >> 1) & 1);
            if (t == 0) mbar_arrive_peer(mb, peer);
            // coefs + self terms in the arrive/wait shadow
            float2 Bf = sm->tabB[l][bidx];
            float2 r0 = sm->ry0[l];
            float c0 = r0.x;
            float co = r ? r0.y : -r0.y;
            u64 TX[2], TY[2], Oxp[2], Oyp[2], Onoyp[2];
            int a0s[2], a1s[2];
            #pragma unroll
            for (int p = 0; p < 2; p++) {
                float2 d0 = cmulf(sm->tabA[l][abase | (p << 1)], Bf);
                float2 d1 = cmulf(sm->tabA[l][abase | (p << 1) | 1], Bf);
                u64 sx  = pack2(d0.x * c0, d1.x * c0);
                u64 sy  = pack2(d0.y * c0, d1.y * c0);
                u64 nsy = pack2(-d0.y * c0, -d1.y * c0);
                Oxp[p]   = pack2(d0.x * co, d1.x * co);
                Oyp[p]   = pack2(d0.y * co, d1.y * co);
                Onoyp[p] = pack2(-d0.y * co, -d1.y * co);
                int a0 = gb ^ (p ? 768 : 0);
                int a1 = a0 ^ 256;
                a0s[p] = a0; a1s[p] = a1;
                u64 VX = pack2(csX[a0 & 2047], csX[a1 & 2047]);
                u64 VY = pack2(csY[a0 & 2047], csY[a1 & 2047]);
                TX[p] = fma2(nsy, VY, mul2(sx, VX));
                TY[p] = fma2(sy, VX, mul2(sx, VY));
            }
            mbar_wait(mb, par);
            #pragma unroll
            for (int p = 0; p < 2; p++) {
                int a0 = a0s[p] ^ 2048, a1 = a1s[p] ^ 2048;
                u64 PX = pack2(ldcg(gfX + a0), ldcg(gfX + a1));
                u64 PY = pack2(ldcg(gfY + a0), ldcg(gfY + a1));
                AX[p] = fma2(Onoyp[p], PY, fma2(Oxp[p], PX, TX[p]));
                AY[p] = fma2(Oyp[p], PX, fma2(Oxp[p], PY, TY[p]));
            }
        }

        // write column (natural order)
        #pragma unroll
        for (int p = 0; p < 2; p++) {
            float2 xs = unpack2(AX[p]), ys = unpack2(AY[p]);
            int n0 = (r << 11) | (((t >> 5) & 0xF) << 7) | ((t & 0x1F) << 2) | (p << 1);
            g_v[col][n0]     = make_float2(xs.x, ys.x);
            g_v[col][n0 | 1] = make_float2(xs.y, ys.y);
        }
        __syncthreads();
        if (t == 0) red_release_add(&g_flag, 1u);
        CLUSTER_ARRIVE();
        CLUSTER_WAIT();
    } else {
        // ================= OUTPUT BLOCK =================
        const int i = (bid - 8) * 512 + t;
        float s0 = 0.f, c0 = 1.f, s1 = 0.f, c1 = 1.f, hb = head_b[0];
        if (i < B) {
            float t0 = sb[i * 8 + 0], t1 = sb[i * 8 + 1];
            sincosf(t0 * 0.5f, &s0, &c0);
            sincosf(t1 * 0.5f, &s1, &c1);
        }
        float hw[12];
        #pragma unroll
        for (int w = 0; w < 12; w++) hw[w] = head_w[w];

        if (t == 0) {
            while (ld_acquire(&g_flag) < 8u) __nanosleep(32);
        }
        __syncthreads();

        // --- Gram: G[j][k] = sum_idx s(idx) v_j conj(v_k) ---
        float2 acc[4][4];
        #pragma unroll
        for (int a = 0; a < 4; a++)
            #pragma unroll
            for (int b = 0; b < 4; b++) acc[a][b] = make_float2(0.f, 0.f);

        for (int idx = t; idx < 4096; idx += 512) {
            float s = 0.f;
            #pragma unroll
            for (int w = 0; w < 12; w++)
                s += ((idx >> (11 - w)) & 1) ? -hw[w] : hw[w];
            float2 v[4];
            #pragma unroll
            for (int a = 0; a < 4; a++) v[a] = g_v[a][idx];
            #pragma unroll
            for (int a = 0; a < 4; a++)
                #pragma unroll
                for (int b = 0; b < 4; b++) {
                    float pr = v[a].x * v[b].x + v[a].y * v[b].y;
                    float pi = v[a].y * v[b].x - v[a].x * v[b].y;
                    acc[a][b].x += s * pr;
                    acc[a][b].y += s * pi;
                }
        }

        float* red = (float*)smem_raw;      // [16][32]
        float* Gs  = red + 16 * 32;         // [32]
        float* flat = reinterpret_cast<float*>(acc);
        const int lane = t & 31, warp = t >> 5;
        #pragma unroll
        for (int comp = 0; comp < 32; comp++) {
            float v = flat[comp];
            #pragma unroll
            for (int off = 16; off; off >>= 1)
                v += __shfl_down_sync(0xffffffff, v, off);
            if (lane == 0) red[warp * 32 + comp] = v;
        }
        __syncthreads();
        if (t < 32) {
            float v = 0.f;
            #pragma unroll
            for (int w = 0; w < 16; w++) v += red[w * 32 + t];
            Gs[t] = v;
        }
        __syncthreads();

        // self-resetting flags for graph replays
        if (t == 0) {
            int d = atomicAdd(&g_done2, 1);
            if (d == nOut - 1) {
                atomicExch(&g_flag, 0u);
                atomicExch(&g_done2, 0);
            }
        }

        // --- per-sample output: out = Re(c^H G c) + bias ---
        if (i < B) {
            float2 c[4];
            c[0] = make_float2(c0 * c1, 0.f);
            c[1] = make_float2(c0 * s1, 0.f);
            c[2] = make_float2(0.f, -s0 * c1);
            c[3] = make_float2(0.f, -s0 * s1);

            float res = hb;
            #pragma unroll
            for (int jj = 0; jj < 4; jj++)
                #pragma unroll
                for (int k = 0; k < 4; k++) {
                    float ccr = c[jj].x * c[k].x + c[jj].y * c[k].y;
                    float cci = c[jj].y * c[k].x - c[jj].x * c[k].y;
                    float gx = Gs[(jj * 4 + k) * 2];
                    float gy = Gs[(jj * 4 + k) * 2 + 1];
                    res += ccr * gx - cci * gy;
                }
            out[i] = res;
        }
    }
}

extern "C" void kernel_launch(void* const* d_in, const int* in_sizes, int n_in,
                              void* d_out, int out_size) {
    const float* state_batch = (const float*)d_in[0];  // (B, 8)
    const float* weights     = (const float*)d_in[1];  // (8, 12, 3)
    const float* head_w      = (const float*)d_in[2];  // (1, 12)
    const float* head_b      = (const float*)d_in[3];  // (1,)
    float* out = (float*)d_out;
    const int B = in_sizes[0] / 8;

    const int smem_bytes = (int)sizeof(SimSmem);
    cudaFuncSetAttribute(fused_kernel, cudaFuncAttributeMaxDynamicSharedMemorySize,
                         smem_bytes);
    int nOut = (B + 511) / 512;
    nOut += (nOut & 1);   // grid must be even for cluster_dims (2,1,1)
    fused_kernel<<<8 + nOut, 512, smem_bytes>>>(weights, head_w, head_b,
                                                state_batch, out, B, nOut);
}